// round 12
// baseline (speedup 1.0000x reference)
#include <cuda_runtime.h>
#include <cuda_fp16.h>
#include <stdint.h>
#include <math.h>

#define BSZ 2
#define NP  2048
#define CH  256
#define FFNC 1024
#define NROW (BSZ*NP)
#define NBLK 512           // persistent IPOT grid (256 per batch, 8 rows each, 1 row/warp)

// ---------------- scratch (device globals; no allocations) ----------------
__device__ __half g_Qh[(size_t)BSZ*NP*NP];   // final transport matrix (fp16), written once
__device__ __half g_Gh[(size_t)BSZ*NP*NP];   // exp(-cost/10) (fp16)
__device__ float g_Xtp[(size_t)BSZ*NP*CH];   // pts feat transposed [b,n,c]
__device__ float g_Xti[(size_t)BSZ*NP*CH];   // img feat transposed [b,n,c]
__device__ float g_imf[(size_t)BSZ*CH*NP];   // img projected feat [b,c,m] (pre-scaled by b)
__device__ float g_xcat[(size_t)BSZ*NP*2*CH];// [pf ; img_att] token-major [b,n,512]
__device__ float g_x[(size_t)BSZ*NP*CH];     // post out-proj (+LN in place)
__device__ float g_h[(size_t)BSZ*NP*FFNC];   // FFN hidden
__device__ float g_y2[(size_t)BSZ*NP*CH];    // FFN out + residual
__device__ float g_pcls[NROW], g_icls[NROW];
__device__ float g_bv[NROW], g_wv[NROW];
__device__ float g_v[3][NROW];               // triple-buffered column sums v = Q^T a

// grid-barrier state (zero-initialized; g_gen monotonic across replays)
__device__ unsigned g_cnt16[16];
__device__ unsigned g_cntm;
__device__ volatile unsigned g_gen;

// ---------------- software grid barrier (all NBLK CTAs co-resident) ----------------
__device__ __forceinline__ void gridbar() {
    __syncthreads();
    if (threadIdx.x == 0) {
        unsigned my = g_gen;
        __threadfence();
        unsigned s = blockIdx.x & 15;                // 16 groups of 32
        if (atomicAdd(&g_cnt16[s], 1) == 31) {
            g_cnt16[s] = 0;
            if (atomicAdd(&g_cntm, 1) == 15) {
                g_cntm = 0;
                __threadfence();
                g_gen = my + 1;
            }
        }
        while (g_gen == my) { __nanosleep(32); }
        __threadfence();
    }
    __syncthreads();
}

// ---------------- transpose [b,C,N] -> [b,N,C] ----------------
__global__ void k_transpose(const float* __restrict__ src, int which) {
    __shared__ float t[32][33];
    int b = blockIdx.z;
    float* dst = which ? g_Xti : g_Xtp;
    const float* s = src + (size_t)b * CH * NP;
    float* d = dst + (size_t)b * NP * CH;
    int n0 = blockIdx.x * 32, c0 = blockIdx.y * 32;
    for (int i = threadIdx.y; i < 32; i += 8)
        t[i][threadIdx.x] = s[(size_t)(c0 + i) * NP + n0 + threadIdx.x];
    __syncthreads();
    for (int i = threadIdx.y; i < 32; i += 8)
        d[(size_t)(n0 + i) * CH + c0 + threadIdx.x] = t[threadIdx.x][i];
}

// ---------------- pcls/icls = sigmoid(max over classes) ----------------
__global__ void k_cls(const float* __restrict__ pc, const float* __restrict__ ic) {
    int idx = blockIdx.x * 256 + threadIdx.x;   // 0..4095
    int b = idx >> 11, n = idx & (NP - 1);
    const float* p = pc + (size_t)b * 10 * NP + n;
    const float* q = ic + (size_t)b * 10 * NP + n;
    float mp = -1e30f, mi = -1e30f;
    #pragma unroll
    for (int c = 0; c < 10; c++) {
        mp = fmaxf(mp, p[(size_t)c * NP]);
        mi = fmaxf(mi, q[(size_t)c * NP]);
    }
    g_pcls[idx] = 1.f / (1.f + expf(-mp));
    g_icls[idx] = 1.f / (1.f + expf(-mi));
}

// ---------------- persistent IPOT: 512 CTAs, 1 row/warp, raw-q slots ----------------
// Warp owns ONE row (Q in 32 packed half2 regs). Deposit of raw q fused into the
// j-loop (no RMW pass, no staging array); an scaled in at the fp32 combine.
__global__ void __launch_bounds__(256, 4) k_ipot_persist(
    const float* __restrict__ ppos, const float* __restrict__ ipos) {
    extern __shared__ float sm[];         // 8KB b + 32KB raw-q slots + 32B an
    float* sh_b = sm;
    __half* sh_q = (__half*)(sm + NP);
    float* sh_an = (float*)(sh_q + 8 * NP);
    int tid = threadIdx.x, lane = tid & 31, wid = tid >> 5;
    int bid = blockIdx.x;
    int batch = bid >> 8, lb = bid & 255;
    int boff = batch * NP;
    int row = lb * 8 + wid;               // this warp's row, fixed for all iters

    float pc = g_pcls[boff + row];
    float an_keep = 0.f;
    unsigned int qreg[32];                // Q for 1 row x 64 cols, packed half2

    // prologue: zero v[1]; 8 cols per block (256 blocks x 8 = 2048 per batch)
    if (tid < 8) g_v[1][boff + lb * 8 + tid] = 0.f;
    gridbar();

    __half* pwh = sh_q + wid * NP;

    for (int t = 1; t <= 100; t++) {
        // b into smem (t>1); zero v[(t+1)%3] (8 cols per block)
        if (t > 1) {
            const float* vr = g_v[(t - 1) % 3] + boff;
            const float* ic = g_icls + boff;
            #pragma unroll
            for (int j = 0; j < 8; j++) {
                int m = tid + 256 * j;
                sh_b[m] = __fdividef(ic[m], __ldcg(vr + m) + 1e-6f);
            }
        }
        if (tid < 8) g_v[(t + 1) % 3][boff + lb * 8 + tid] = 0.f;
        __syncthreads();

        size_t base = (size_t)(boff + row) * NP;
        float u = 0.f;

        if (t == 1) {
            float2 pp = ((const float2*)ppos)[boff + row];
            const float2* ip = (const float2*)ipos + boff;
            #pragma unroll
            for (int j = 0; j < 8; j++) {
                int c = (j * 32 + lane) * 8;
                float qn[8];
                #pragma unroll
                for (int h = 0; h < 8; h++) {
                    float2 q2 = ip[c + h];
                    float dx = pp.x - q2.x, dy = pp.y - q2.y;
                    qn[h] = expf(-0.1f * sqrtf(dx * dx + dy * dy));
                }
                uint4 go; __half2* goh = (__half2*)&go;
                uint4 qo; __half2* qoh = (__half2*)&qo;
                #pragma unroll
                for (int h = 0; h < 4; h++) {
                    goh[h] = __floats2half2_rn(qn[2 * h], qn[2 * h + 1]);
                    float a0 = fmaxf(qn[2 * h], 1e-6f), a1 = fmaxf(qn[2 * h + 1], 1e-6f);
                    __half2 qp = __floats2half2_rn(a0, a1);
                    qoh[h] = qp;
                    qreg[j * 4 + h] = *(unsigned int*)&qp;
                    u += a0 + a1;
                }
                *(uint4*)(g_Gh + base + c) = go;
                *(uint4*)(pwh + c) = qo;          // raw q deposit
            }
            u *= (1.0f / NP);
        } else {
            float ap = an_keep;
            #pragma unroll
            for (int j = 0; j < 8; j++) {
                int c = (j * 32 + lane) * 8;
                uint4 gq = *(const uint4*)(g_Gh + base + c);
                const __half2* gh = (const __half2*)&gq;
                float4 b0 = *(const float4*)(sh_b + c);
                float4 b1 = *(const float4*)(sh_b + c + 4);
                float bb[8] = {b0.x, b0.y, b0.z, b0.w, b1.x, b1.y, b1.z, b1.w};
                uint4 qo; __half2* qoh = (__half2*)&qo;
                #pragma unroll
                for (int h = 0; h < 4; h++) {
                    float2 gf = __half22float2(gh[h]);
                    __half2 qp = *(__half2*)&qreg[j * 4 + h];
                    float2 qf = __half22float2(qp);
                    float n0 = fmaxf(gf.x * (ap * qf.x * bb[2 * h]), 1e-6f);
                    float n1 = fmaxf(gf.y * (ap * qf.y * bb[2 * h + 1]), 1e-6f);
                    __half2 np2 = __floats2half2_rn(n0, n1);
                    qoh[h] = np2;
                    qreg[j * 4 + h] = *(unsigned int*)&np2;
                    u += n0 * bb[2 * h] + n1 * bb[2 * h + 1];
                }
                *(uint4*)(pwh + c) = qo;          // raw q deposit
            }
        }
        #pragma unroll
        for (int o = 16; o; o >>= 1) u += __shfl_xor_sync(0xffffffffu, u, o);
        float an = __fdividef(pc, u + 1e-6f);
        an_keep = an;
        if (lane == 0) sh_an[wid] = an;
        __syncthreads();

        // combine 8 raw-q slots scaled by an[w], flush once per block (fp32)
        float aw[8];
        #pragma unroll
        for (int w = 0; w < 8; w++) aw[w] = sh_an[w];
        float* vw = g_v[t % 3] + boff;
        #pragma unroll
        for (int jj = 0; jj < 4; jj++) {
            int m = 2 * tid + 512 * jj;
            float s0 = 0.f, s1 = 0.f;
            #pragma unroll
            for (int w = 0; w < 8; w++) {
                __half2 hv = *(const __half2*)(sh_q + w * NP + m);
                float2 f = __half22float2(hv);
                s0 += aw[w] * f.x; s1 += aw[w] * f.y;
            }
            atomicAdd(vw + m, s0);
            atomicAdd(vw + m + 1, s1);
        }
        gridbar();
    }

    // epilogue: b_final = icls/(v[1]+eps) -> smem (+ g_bv once per batch)
    {
        const float* vf = g_v[1] + boff;
        const float* ic = g_icls + boff;
        #pragma unroll
        for (int j = 0; j < 8; j++) {
            int m = tid + 256 * j;
            float bf = __fdividef(ic[m], __ldcg(vf + m) + 1e-6f);
            sh_b[m] = bf;
            if (lb == 0) g_bv[boff + m] = bf;
        }
    }
    __syncthreads();

    // write Q to global (once) + row-normalization scale
    {
        size_t base = (size_t)(boff + row) * NP;
        float srs = 0.f;
        #pragma unroll
        for (int j = 0; j < 8; j++) {
            int c = (j * 32 + lane) * 8;
            uint4 qo;
            qo.x = qreg[j * 4 + 0]; qo.y = qreg[j * 4 + 1];
            qo.z = qreg[j * 4 + 2]; qo.w = qreg[j * 4 + 3];
            *(uint4*)(g_Qh + base + c) = qo;
            float4 b0 = *(const float4*)(sh_b + c);
            float4 b1 = *(const float4*)(sh_b + c + 4);
            float bb[8] = {b0.x, b0.y, b0.z, b0.w, b1.x, b1.y, b1.z, b1.w};
            #pragma unroll
            for (int h = 0; h < 4; h++) {
                __half2 qp = *(__half2*)&qreg[j * 4 + h];
                float2 qf = __half22float2(qp);
                srs += qf.x * bb[2 * h] + qf.y * bb[2 * h + 1];
            }
        }
        #pragma unroll
        for (int o = 16; o; o >>= 1) srs += __shfl_xor_sync(0xffffffffu, srs, o);
        if (lane == 0) {
            float a = an_keep;
            g_wv[boff + row] = a / fmaxf(a * srs, 1e-12f);
        }
    }
}

// ---------------- tiled GEMM 64x128x32, 4x8/thread: C[i,j] = sum_k A[i,k]*B[j,k] ----------------
// MODE 0: pf   A=g_Xtp[b](2048x256)   B=Wp     -> xcat[:, :256] (+bp+bqp+Wqp·ppos(i))
// MODE 1: imf  A=Wi(256x256)          B=g_Xti  -> g_imf[b,c,m]  (+bi+bkp+Wkp·ipos(j)) * bv[j]
// MODE 2: att  A=g_Qh[b] (fp16)       B=g_imf  -> xcat[:,256:]  (*wv[i])
// MODE 3: proj A=g_xcat[b](2048x512)  B=Wout   -> g_x           (+bout)
// MODE 4: ffn1 A=g_x[b](2048x256)     B=Wf1    -> g_h           relu(+bf1)
// MODE 5: ffn2 A=g_h[b](2048x1024)    B=Wf2    -> g_y2          (+bf2 + g_x residual)
template<int MODE>
__global__ void __launch_bounds__(256) k_gemm(const float* __restrict__ e0,
                                              const float* __restrict__ p0,
                                              const float* __restrict__ p1,
                                              const float* __restrict__ p2,
                                              const float* __restrict__ p3) {
    constexpr int BM = 64, BN = 128, BK = 32;
    constexpr int K = (MODE == 0 || MODE == 1 || MODE == 4) ? 256 :
                      (MODE == 2 ? 2048 : (MODE == 3 ? 512 : 1024));
    int b = blockIdx.z;
    const float* A = nullptr; const float* Bm;
    if constexpr (MODE == 0)      { A = g_Xtp + (size_t)b * NP * CH;  Bm = e0; }
    else if constexpr (MODE == 1) { A = e0;                           Bm = g_Xti + (size_t)b * NP * CH; }
    else if constexpr (MODE == 2) { Bm = g_imf + (size_t)b * CH * NP; }
    else if constexpr (MODE == 3) { A = g_xcat + (size_t)b * NP * 2 * CH; Bm = e0; }
    else if constexpr (MODE == 4) { A = g_x + (size_t)b * NP * CH;    Bm = e0; }
    else                          { A = g_h + (size_t)b * NP * FFNC;  Bm = e0; }

    __shared__ float Asm[BK][BM + 4];
    __shared__ float Bsm[BK][BN + 4];
    int i0 = blockIdx.y * BM, j0 = blockIdx.x * BN;
    int tx = threadIdx.x & 15, ty = threadIdx.x >> 4;
    float acc[4][8];
    #pragma unroll
    for (int r = 0; r < 4; r++)
        #pragma unroll
        for (int c = 0; c < 8; c++) acc[r][c] = 0.f;

    for (int k0 = 0; k0 < K; k0 += BK) {
        if constexpr (MODE == 2) {
            const __half* Ah = g_Qh + (size_t)b * NP * NP;
            int f = threadIdx.x;
            int i = f >> 2, k8 = (f & 3) * 8;
            uint4 av = *(const uint4*)(Ah + (size_t)(i0 + i) * K + k0 + k8);
            const __half2* ah = (const __half2*)&av;
            #pragma unroll
            for (int h = 0; h < 4; h++) {
                float2 af = __half22float2(ah[h]);
                Asm[k8 + 2 * h][i] = af.x;
                Asm[k8 + 2 * h + 1][i] = af.y;
            }
        } else {
            #pragma unroll
            for (int s = 0; s < 2; s++) {
                int f4 = threadIdx.x + s * 256;
                int i = f4 >> 3, k4 = f4 & 7;
                float4 v = *(const float4*)(A + (size_t)(i0 + i) * K + k0 + k4 * 4);
                Asm[k4 * 4 + 0][i] = v.x; Asm[k4 * 4 + 1][i] = v.y;
                Asm[k4 * 4 + 2][i] = v.z; Asm[k4 * 4 + 3][i] = v.w;
            }
        }
        #pragma unroll
        for (int s = 0; s < 4; s++) {
            int f4 = threadIdx.x + s * 256;
            int j = f4 >> 3, k4 = f4 & 7;
            float4 v = *(const float4*)(Bm + (size_t)(j0 + j) * K + k0 + k4 * 4);
            Bsm[k4 * 4 + 0][j] = v.x; Bsm[k4 * 4 + 1][j] = v.y;
            Bsm[k4 * 4 + 2][j] = v.z; Bsm[k4 * 4 + 3][j] = v.w;
        }
        __syncthreads();
        #pragma unroll
        for (int kk = 0; kk < BK; kk++) {
            float4 a0 = *(const float4*)&Asm[kk][ty * 4];
            float4 b0 = *(const float4*)&Bsm[kk][tx * 8];
            float4 b1 = *(const float4*)&Bsm[kk][tx * 8 + 4];
            float ar[4] = {a0.x, a0.y, a0.z, a0.w};
            float br[8] = {b0.x, b0.y, b0.z, b0.w, b1.x, b1.y, b1.z, b1.w};
            #pragma unroll
            for (int r = 0; r < 4; r++)
                #pragma unroll
                for (int c = 0; c < 8; c++) acc[r][c] += ar[r] * br[c];
        }
        __syncthreads();
    }

    int j = j0 + tx * 8;
    float bc[8], w0c[8], w1c[8], ppx[8], ppy[8], bvc[8];
    if constexpr (MODE == 0) {
        #pragma unroll
        for (int c = 0; c < 8; c++) {
            bc[c] = p0[j + c] + p1[j + c];
            w0c[c] = p2[2 * (j + c)];
            w1c[c] = p2[2 * (j + c) + 1];
        }
    } else if constexpr (MODE == 1) {
        #pragma unroll
        for (int c = 0; c < 8; c++) {
            float2 pp = ((const float2*)p3)[b * NP + j + c];
            ppx[c] = pp.x; ppy[c] = pp.y;
            bvc[c] = g_bv[b * NP + j + c];
        }
    } else if constexpr (MODE == 3 || MODE == 4 || MODE == 5) {
        #pragma unroll
        for (int c = 0; c < 8; c++) bc[c] = p0[j + c];
    }

    #pragma unroll
    for (int r = 0; r < 4; r++) {
        int i = i0 + ty * 4 + r;
        float vr[8];
        #pragma unroll
        for (int c = 0; c < 8; c++) vr[c] = acc[r][c];
        if constexpr (MODE == 0) {
            float2 pp = ((const float2*)p3)[b * NP + i];
            #pragma unroll
            for (int c = 0; c < 8; c++) vr[c] += bc[c] + w0c[c] * pp.x + w1c[c] * pp.y;
            float* o = g_xcat + ((size_t)(b * NP + i)) * (2 * CH) + j;
            *(float4*)o = make_float4(vr[0], vr[1], vr[2], vr[3]);
            *(float4*)(o + 4) = make_float4(vr[4], vr[5], vr[6], vr[7]);
        } else if constexpr (MODE == 1) {
            float bia = p0[i] + p1[i];
            float w0 = p2[2 * i], w1 = p2[2 * i + 1];
            #pragma unroll
            for (int c = 0; c < 8; c++) vr[c] = (vr[c] + bia + w0 * ppx[c] + w1 * ppy[c]) * bvc[c];
            float* o = g_imf + (size_t)b * CH * NP + (size_t)i * NP + j;
            *(float4*)o = make_float4(vr[0], vr[1], vr[2], vr[3]);
            *(float4*)(o + 4) = make_float4(vr[4], vr[5], vr[6], vr[7]);
        } else if constexpr (MODE == 2) {
            float w = g_wv[b * NP + i];
            #pragma unroll
            for (int c = 0; c < 8; c++) vr[c] *= w;
            float* o = g_xcat + ((size_t)(b * NP + i)) * (2 * CH) + CH + j;
            *(float4*)o = make_float4(vr[0], vr[1], vr[2], vr[3]);
            *(float4*)(o + 4) = make_float4(vr[4], vr[5], vr[6], vr[7]);
        } else if constexpr (MODE == 3) {
            #pragma unroll
            for (int c = 0; c < 8; c++) vr[c] += bc[c];
            float* o = g_x + ((size_t)(b * NP + i)) * CH + j;
            *(float4*)o = make_float4(vr[0], vr[1], vr[2], vr[3]);
            *(float4*)(o + 4) = make_float4(vr[4], vr[5], vr[6], vr[7]);
        } else if constexpr (MODE == 4) {
            #pragma unroll
            for (int c = 0; c < 8; c++) vr[c] = fmaxf(vr[c] + bc[c], 0.f);
            float* o = g_h + ((size_t)(b * NP + i)) * FFNC + j;
            *(float4*)o = make_float4(vr[0], vr[1], vr[2], vr[3]);
            *(float4*)(o + 4) = make_float4(vr[4], vr[5], vr[6], vr[7]);
        } else {
            const float* rsd = g_x + ((size_t)(b * NP + i)) * CH + j;
            float4 r0 = *(const float4*)rsd, r1 = *(const float4*)(rsd + 4);
            vr[0] += bc[0] + r0.x; vr[1] += bc[1] + r0.y; vr[2] += bc[2] + r0.z; vr[3] += bc[3] + r0.w;
            vr[4] += bc[4] + r1.x; vr[5] += bc[5] + r1.y; vr[6] += bc[6] + r1.z; vr[7] += bc[7] + r1.w;
            float* o = g_y2 + ((size_t)(b * NP + i)) * CH + j;
            *(float4*)o = make_float4(vr[0], vr[1], vr[2], vr[3]);
            *(float4*)(o + 4) = make_float4(vr[4], vr[5], vr[6], vr[7]);
        }
    }
}

// ---------------- LayerNorm in place on g_x ----------------
__global__ void k_ln(const float* __restrict__ gamma, const float* __restrict__ beta) {
    int row = blockIdx.x * 8 + (threadIdx.x >> 5);
    int lane = threadIdx.x & 31;
    float* x = g_x + (size_t)row * CH + lane * 8;
    float4 v0 = *(float4*)x;
    float4 v1 = *(float4*)(x + 4);
    float s = v0.x + v0.y + v0.z + v0.w + v1.x + v1.y + v1.z + v1.w;
    float s2 = v0.x * v0.x + v0.y * v0.y + v0.z * v0.z + v0.w * v0.w +
               v1.x * v1.x + v1.y * v1.y + v1.z * v1.z + v1.w * v1.w;
    #pragma unroll
    for (int o = 16; o; o >>= 1) {
        s  += __shfl_xor_sync(0xffffffffu, s, o);
        s2 += __shfl_xor_sync(0xffffffffu, s2, o);
    }
    float mu = s * (1.f / CH);
    float var = s2 * (1.f / CH) - mu * mu;
    float inv = rsqrtf(var + 1e-5f);
    int c = lane * 8;
    float4 g0 = *(const float4*)(gamma + c), g1 = *(const float4*)(gamma + c + 4);
    float4 b0 = *(const float4*)(beta + c),  b1 = *(const float4*)(beta + c + 4);
    v0.x = (v0.x - mu) * inv * g0.x + b0.x; v0.y = (v0.y - mu) * inv * g0.y + b0.y;
    v0.z = (v0.z - mu) * inv * g0.z + b0.z; v0.w = (v0.w - mu) * inv * g0.w + b0.w;
    v1.x = (v1.x - mu) * inv * g1.x + b1.x; v1.y = (v1.y - mu) * inv * g1.y + b1.y;
    v1.z = (v1.z - mu) * inv * g1.z + b1.z; v1.w = (v1.w - mu) * inv * g1.w + b1.w;
    *(float4*)x = v0;
    *(float4*)(x + 4) = v1;
}

// ---------------- final LN + prediction head + outputs ----------------
__global__ void k_final(const float* __restrict__ gamma, const float* __restrict__ beta,
                        const float* __restrict__ Wpred, const float* __restrict__ bpred,
                        const float* __restrict__ ppos,
                        float* __restrict__ out_x, float* __restrict__ out_np,
                        float* __restrict__ out_c) {
    int row = blockIdx.x * 8 + (threadIdx.x >> 5);
    int lane = threadIdx.x & 31;
    int b = row >> 11, n = row & (NP - 1);
    const float* y = g_y2 + (size_t)row * CH + lane * 8;
    float4 v0 = *(const float4*)y;
    float4 v1 = *(const float4*)(y + 4);
    float s = v0.x + v0.y + v0.z + v0.w + v1.x + v1.y + v1.z + v1.w;
    float s2 = v0.x * v0.x + v0.y * v0.y + v0.z * v0.z + v0.w * v0.w +
               v1.x * v1.x + v1.y * v1.y + v1.z * v1.z + v1.w * v1.w;
    #pragma unroll
    for (int o = 16; o; o >>= 1) {
        s  += __shfl_xor_sync(0xffffffffu, s, o);
        s2 += __shfl_xor_sync(0xffffffffu, s2, o);
    }
    float mu = s * (1.f / CH);
    float var = s2 * (1.f / CH) - mu * mu;
    float inv = rsqrtf(var + 1e-5f);
    int c = lane * 8;
    float4 g0 = *(const float4*)(gamma + c), g1 = *(const float4*)(gamma + c + 4);
    float4 b0 = *(const float4*)(beta + c),  b1 = *(const float4*)(beta + c + 4);
    v0.x = (v0.x - mu) * inv * g0.x + b0.x; v0.y = (v0.y - mu) * inv * g0.y + b0.y;
    v0.z = (v0.z - mu) * inv * g0.z + b0.z; v0.w = (v0.w - mu) * inv * g0.w + b0.w;
    v1.x = (v1.x - mu) * inv * g1.x + b1.x; v1.y = (v1.y - mu) * inv * g1.y + b1.y;
    v1.z = (v1.z - mu) * inv * g1.z + b1.z; v1.w = (v1.w - mu) * inv * g1.w + b1.w;

    float4 w00 = *(const float4*)(Wpred + c),      w01 = *(const float4*)(Wpred + c + 4);
    float4 w10 = *(const float4*)(Wpred + CH + c), w11 = *(const float4*)(Wpred + CH + c + 4);
    float d0 = v0.x * w00.x + v0.y * w00.y + v0.z * w00.z + v0.w * w00.w +
               v1.x * w01.x + v1.y * w01.y + v1.z * w01.z + v1.w * w01.w;
    float d1 = v0.x * w10.x + v0.y * w10.y + v0.z * w10.z + v0.w * w10.w +
               v1.x * w11.x + v1.y * w11.y + v1.z * w11.z + v1.w * w11.w;
    #pragma unroll
    for (int o = 16; o; o >>= 1) {
        d0 += __shfl_xor_sync(0xffffffffu, d0, o);
        d1 += __shfl_xor_sync(0xffffffffu, d1, o);
    }
    float* ox = out_x + (size_t)b * CH * NP + n;
    ox[(size_t)(c + 0) * NP] = v0.x; ox[(size_t)(c + 1) * NP] = v0.y;
    ox[(size_t)(c + 2) * NP] = v0.z; ox[(size_t)(c + 3) * NP] = v0.w;
    ox[(size_t)(c + 4) * NP] = v1.x; ox[(size_t)(c + 5) * NP] = v1.y;
    ox[(size_t)(c + 6) * NP] = v1.z; ox[(size_t)(c + 7) * NP] = v1.w;
    if (lane == 0) {
        float2 pp = ((const float2*)ppos)[b * NP + n];
        float c0 = d0 + bpred[0] + pp.x;
        float c1 = d1 + bpred[1] + pp.y;
        out_c[(size_t)b * 2 * NP + n] = c0;
        out_c[(size_t)b * 2 * NP + NP + n] = c1;
        ((float2*)out_np)[b * NP + n] = make_float2(c0, c1);
    }
}

// ---------------- launch ----------------
extern "C" void kernel_launch(void* const* d_in, const int* in_sizes, int n_in,
                              void* d_out, int out_size) {
    const float* ptsf   = (const float*)d_in[0];
    const float* ppos   = (const float*)d_in[1];
    const float* imgf   = (const float*)d_in[2];
    const float* ipos   = (const float*)d_in[3];
    const float* ptscls = (const float*)d_in[4];
    const float* imgcls = (const float*)d_in[5];
    const float* Wp  = (const float*)d_in[6];  const float* bp  = (const float*)d_in[7];
    const float* Wi  = (const float*)d_in[8];  const float* bi  = (const float*)d_in[9];
    const float* Wqp = (const float*)d_in[10]; const float* bqp = (const float*)d_in[11];
    const float* Wkp = (const float*)d_in[12]; const float* bkp = (const float*)d_in[13];
    const float* Wout = (const float*)d_in[14]; const float* bout = (const float*)d_in[15];
    const float* gout = (const float*)d_in[16]; const float* betaout = (const float*)d_in[17];
    const float* Wf1 = (const float*)d_in[18]; const float* bf1 = (const float*)d_in[19];
    const float* Wf2 = (const float*)d_in[20]; const float* bf2 = (const float*)d_in[21];
    const float* gln = (const float*)d_in[22]; const float* bln = (const float*)d_in[23];
    const float* Wpred = (const float*)d_in[24]; const float* bpred = (const float*)d_in[25];

    float* out    = (float*)d_out;
    float* out_x  = out;                                   // [2,256,2048]
    float* out_np = out + (size_t)BSZ * CH * NP;           // [2,2048,2]
    float* out_c  = out_np + (size_t)BSZ * NP * 2;         // [2,2,2048]

    const int IPOT_SMEM = NP * (int)sizeof(float) + 8 * NP * (int)sizeof(__half)
                        + 8 * (int)sizeof(float);          // ~40 KB
    cudaFuncSetAttribute(k_ipot_persist, cudaFuncAttributeMaxDynamicSharedMemorySize, IPOT_SMEM);

    dim3 tb(32, 8);
    k_cls<<<NROW / 256, 256>>>(ptscls, imgcls);                    // launch 1
    k_transpose<<<dim3(NP / 32, CH / 32, BSZ), tb>>>(ptsf, 0);     // launch 2
    k_transpose<<<dim3(NP / 32, CH / 32, BSZ), tb>>>(imgf, 1);     // launch 3

    // launch 4 (ncu capture slot): ALL 100 IPOT iterations, 512 CTAs, 1 row/warp
    k_ipot_persist<<<NBLK, 256, IPOT_SMEM>>>(ppos, ipos);

    // projections + positional embeddings
    k_gemm<0><<<dim3(CH / 128, NP / 64, BSZ), 256>>>(Wp, bp, bqp, Wqp, ppos);
    k_gemm<1><<<dim3(NP / 128, CH / 64, BSZ), 256>>>(Wi, bi, bkp, Wkp, ipos);  // *bv folded

    // attention GEMM: img_att = w ⊙ (Q_fp16 @ imf_scaled^T)
    k_gemm<2><<<dim3(CH / 128, NP / 64, BSZ), 256>>>(nullptr, nullptr, nullptr, nullptr, nullptr);
    // out projection + LN
    k_gemm<3><<<dim3(CH / 128, NP / 64, BSZ), 256>>>(Wout, bout, nullptr, nullptr, nullptr);
    k_ln<<<NROW / 8, 256>>>(gout, betaout);
    // FFN
    k_gemm<4><<<dim3(FFNC / 128, NP / 64, BSZ), 256>>>(Wf1, bf1, nullptr, nullptr, nullptr);
    k_gemm<5><<<dim3(CH / 128, NP / 64, BSZ), 256>>>(Wf2, bf2, nullptr, nullptr, nullptr);
    // final LN + head + outputs
    k_final<<<NROW / 8, 256>>>(gln, bln, Wpred, bpred, ppos, out_x, out_np, out_c);
}

// round 13
// speedup vs baseline: 1.0726x; 1.0726x over previous
#include <cuda_runtime.h>
#include <cuda_fp16.h>
#include <stdint.h>
#include <math.h>

#define BSZ 2
#define NP  2048
#define CH  256
#define FFNC 1024
#define NROW (BSZ*NP)
#define NBLK 256           // persistent IPOT grid (128 per batch, 16 rows each)

// ---------------- scratch (device globals; no allocations) ----------------
__device__ __half g_Qh[(size_t)BSZ*NP*NP];   // IPOT transport matrix (fp16), in place
__device__ __half g_Gh[(size_t)BSZ*NP*NP];   // exp(-cost/10) (fp16)
__device__ float g_Xtp[(size_t)BSZ*NP*CH];   // pts feat transposed [b,n,c]
__device__ float g_Xti[(size_t)BSZ*NP*CH];   // img feat transposed [b,n,c]
__device__ float g_imf[(size_t)BSZ*CH*NP];   // img projected feat [b,c,m] (pre-scaled by b)
__device__ float g_xcat[(size_t)BSZ*NP*2*CH];// [pf ; img_att] token-major [b,n,512]
__device__ float g_x[(size_t)BSZ*NP*CH];     // post out-proj (+LN in place)
__device__ float g_h[(size_t)BSZ*NP*FFNC];   // FFN hidden
__device__ float g_y2[(size_t)BSZ*NP*CH];    // FFN out + residual
__device__ float g_pcls[NROW], g_icls[NROW];
__device__ float g_bv[NROW], g_wv[NROW];
__device__ float g_v[3][NROW];               // triple-buffered column sums v = Q^T a

// grid-barrier state (zero-initialized; g_gen monotonic across replays)
__device__ unsigned g_cnt8[8];
__device__ unsigned g_cntm;
__device__ volatile unsigned g_gen;

// ---------------- software grid barrier (all NBLK CTAs co-resident) ----------------
__device__ __forceinline__ void gridbar() {
    __syncthreads();
    if (threadIdx.x == 0) {
        unsigned my = g_gen;
        __threadfence();
        unsigned s = blockIdx.x & 7;                 // 8 groups of 32
        if (atomicAdd(&g_cnt8[s], 1) == 31) {
            g_cnt8[s] = 0;
            if (atomicAdd(&g_cntm, 1) == 7) {
                g_cntm = 0;
                __threadfence();
                g_gen = my + 1;
            }
        }
        while (g_gen == my) { __nanosleep(32); }
        __threadfence();
    }
    __syncthreads();
}

// ---------------- transpose [b,C,N] -> [b,N,C] ----------------
__global__ void k_transpose(const float* __restrict__ src, int which) {
    __shared__ float t[32][33];
    int b = blockIdx.z;
    float* dst = which ? g_Xti : g_Xtp;
    const float* s = src + (size_t)b * CH * NP;
    float* d = dst + (size_t)b * NP * CH;
    int n0 = blockIdx.x * 32, c0 = blockIdx.y * 32;
    for (int i = threadIdx.y; i < 32; i += 8)
        t[i][threadIdx.x] = s[(size_t)(c0 + i) * NP + n0 + threadIdx.x];
    __syncthreads();
    for (int i = threadIdx.y; i < 32; i += 8)
        d[(size_t)(n0 + i) * CH + c0 + threadIdx.x] = t[threadIdx.x][i];
}

// ---------------- pcls/icls = sigmoid(max over classes) ----------------
__global__ void k_cls(const float* __restrict__ pc, const float* __restrict__ ic) {
    int idx = blockIdx.x * 256 + threadIdx.x;   // 0..4095
    int b = idx >> 11, n = idx & (NP - 1);
    const float* p = pc + (size_t)b * 10 * NP + n;
    const float* q = ic + (size_t)b * 10 * NP + n;
    float mp = -1e30f, mi = -1e30f;
    #pragma unroll
    for (int c = 0; c < 10; c++) {
        mp = fmaxf(mp, p[(size_t)c * NP]);
        mi = fmaxf(mi, q[(size_t)c * NP]);
    }
    g_pcls[idx] = 1.f / (1.f + expf(-mp));
    g_icls[idx] = 1.f / (1.f + expf(-mi));
}

// ---------------- persistent IPOT (R8 structure, best measured) ----------------
__global__ void __launch_bounds__(256, 2) k_ipot_persist(
    const float* __restrict__ ppos, const float* __restrict__ ipos) {
    extern __shared__ float sm[];         // 8KB fp32 b + 32KB fp16 slots = 40KB
    float* sh_b = sm;
    __half* sh_ph = (__half*)(sm + NP);
    int tid = threadIdx.x, lane = tid & 31, wid = tid >> 5;
    int bid = blockIdx.x;
    int batch = bid >> 7, lb = bid & 127;
    int boff = batch * NP;
    int row0 = lb * 16;

    float pc0 = g_pcls[boff + row0 + wid];
    float pc1 = g_pcls[boff + row0 + wid + 8];
    float an_keep[2];
    an_keep[0] = 0.f; an_keep[1] = 0.f;

    #pragma unroll
    for (int j = 0; j < 8; j++) g_v[1][boff + tid + 256 * j] = 0.f;
    gridbar();

    for (int t = 1; t <= 100; t++) {
        {
            float* vz = g_v[(t + 1) % 3] + boff;
            if (t == 1) {
                #pragma unroll
                for (int j = 0; j < 8; j++) vz[tid + 256 * j] = 0.f;
            } else {
                const float* vr = g_v[(t - 1) % 3] + boff;
                const float* ic = g_icls + boff;
                #pragma unroll
                for (int j = 0; j < 8; j++) {
                    int m = tid + 256 * j;
                    sh_b[m] = __fdividef(ic[m], __ldcg(vr + m) + 1e-6f);
                    vz[m] = 0.f;
                }
            }
        }
        __syncthreads();

        __half* pwh = sh_ph + wid * NP;
        #pragma unroll
        for (int rr = 0; rr < 2; rr++) {
            int row = row0 + wid + rr * 8;
            size_t base = (size_t)(boff + row) * NP;
            float qv[8][8];
            float u = 0.f;

            if (t == 1) {
                float2 pp = ((const float2*)ppos)[boff + row];
                const float2* ip = (const float2*)ipos + boff;
                #pragma unroll
                for (int j = 0; j < 8; j++) {
                    int c = (j * 32 + lane) * 8;
                    float qn[8];
                    #pragma unroll
                    for (int h = 0; h < 8; h++) {
                        float2 q2 = ip[c + h];
                        float dx = pp.x - q2.x, dy = pp.y - q2.y;
                        qn[h] = expf(-0.1f * sqrtf(dx * dx + dy * dy));
                    }
                    uint4 go; __half2* goh = (__half2*)&go;
                    uint4 qo; __half2* qoh = (__half2*)&qo;
                    #pragma unroll
                    for (int h = 0; h < 4; h++) {
                        goh[h] = __floats2half2_rn(qn[2 * h], qn[2 * h + 1]);
                        float a0 = fmaxf(qn[2 * h], 1e-6f), a1 = fmaxf(qn[2 * h + 1], 1e-6f);
                        qoh[h] = __floats2half2_rn(a0, a1);
                        qv[j][2 * h] = a0; qv[j][2 * h + 1] = a1;
                        u += a0 + a1;
                    }
                    *(uint4*)(g_Gh + base + c) = go;
                    *(uint4*)(g_Qh + base + c) = qo;
                }
                u *= (1.0f / NP);
            } else {
                float ap = an_keep[rr];
                #pragma unroll
                for (int j = 0; j < 8; j++) {
                    int c = (j * 32 + lane) * 8;
                    uint4 gq = *(const uint4*)(g_Gh + base + c);
                    uint4 qq = *(const uint4*)(g_Qh + base + c);
                    const __half2* gh = (const __half2*)&gq;
                    const __half2* qh = (const __half2*)&qq;
                    float4 b0 = *(const float4*)(sh_b + c);
                    float4 b1 = *(const float4*)(sh_b + c + 4);
                    float bb[8] = {b0.x, b0.y, b0.z, b0.w, b1.x, b1.y, b1.z, b1.w};
                    uint4 qo; __half2* qoh = (__half2*)&qo;
                    #pragma unroll
                    for (int h = 0; h < 4; h++) {
                        float2 gf = __half22float2(gh[h]);
                        float2 qf = __half22float2(qh[h]);
                        float n0 = fmaxf(gf.x * (ap * qf.x * bb[2 * h]), 1e-6f);
                        float n1 = fmaxf(gf.y * (ap * qf.y * bb[2 * h + 1]), 1e-6f);
                        qoh[h] = __floats2half2_rn(n0, n1);
                        qv[j][2 * h] = n0; qv[j][2 * h + 1] = n1;
                        u += n0 * bb[2 * h] + n1 * bb[2 * h + 1];
                    }
                    *(uint4*)(g_Qh + base + c) = qo;
                }
            }
            #pragma unroll
            for (int o = 16; o; o >>= 1) u += __shfl_xor_sync(0xffffffffu, u, o);
            float an = __fdividef((rr == 0 ? pc0 : pc1), u + 1e-6f);
            an_keep[rr] = an;

            if (rr == 0) {
                #pragma unroll
                for (int j = 0; j < 8; j++) {
                    int c = (j * 32 + lane) * 8;
                    uint4 st; __half2* sth = (__half2*)&st;
                    #pragma unroll
                    for (int h = 0; h < 4; h++)
                        sth[h] = __floats2half2_rn(an * qv[j][2 * h], an * qv[j][2 * h + 1]);
                    *(uint4*)(pwh + c) = st;
                }
            } else {
                #pragma unroll
                for (int j = 0; j < 8; j++) {
                    int c = (j * 32 + lane) * 8;
                    uint4 old = *(uint4*)(pwh + c);
                    __half2* oh = (__half2*)&old;
                    uint4 st; __half2* sth = (__half2*)&st;
                    #pragma unroll
                    for (int h = 0; h < 4; h++) {
                        float2 f = __half22float2(oh[h]);
                        sth[h] = __floats2half2_rn(f.x + an * qv[j][2 * h],
                                                   f.y + an * qv[j][2 * h + 1]);
                    }
                    *(uint4*)(pwh + c) = st;
                }
            }
        }
        __syncthreads();

        float* vw = g_v[t % 3] + boff;
        #pragma unroll
        for (int jj = 0; jj < 4; jj++) {
            int m = 2 * tid + 512 * jj;
            float s0 = 0.f, s1 = 0.f;
            #pragma unroll
            for (int w = 0; w < 8; w++) {
                __half2 hv = *(const __half2*)(sh_ph + w * NP + m);
                float2 f = __half22float2(hv);
                s0 += f.x; s1 += f.y;
            }
            atomicAdd(vw + m, s0);
            atomicAdd(vw + m + 1, s1);
        }
        gridbar();
    }

    // epilogue: b_final -> smem (+ g_bv once per batch)
    {
        const float* vf = g_v[1] + boff;
        const float* ic = g_icls + boff;
        #pragma unroll
        for (int j = 0; j < 8; j++) {
            int m = tid + 256 * j;
            float bf = __fdividef(ic[m], __ldcg(vf + m) + 1e-6f);
            sh_b[m] = bf;
            if (lb == 0) g_bv[boff + m] = bf;
        }
    }
    __syncthreads();

    // row-normalization scale
    #pragma unroll
    for (int rr = 0; rr < 2; rr++) {
        int row = row0 + wid + rr * 8;
        size_t base = (size_t)(boff + row) * NP;
        float srs = 0.f;
        #pragma unroll
        for (int j = 0; j < 8; j++) {
            int c = (j * 32 + lane) * 8;
            uint4 qq = *(const uint4*)(g_Qh + base + c);
            const __half2* qh = (const __half2*)&qq;
            float4 b0 = *(const float4*)(sh_b + c);
            float4 b1 = *(const float4*)(sh_b + c + 4);
            float bb[8] = {b0.x, b0.y, b0.z, b0.w, b1.x, b1.y, b1.z, b1.w};
            #pragma unroll
            for (int h = 0; h < 4; h++) {
                float2 qf = __half22float2(qh[h]);
                srs += qf.x * bb[2 * h] + qf.y * bb[2 * h + 1];
            }
        }
        #pragma unroll
        for (int o = 16; o; o >>= 1) srs += __shfl_xor_sync(0xffffffffu, srs, o);
        if (lane == 0) {
            float a = an_keep[rr];
            g_wv[boff + row] = a / fmaxf(a * srs, 1e-12f);
        }
    }
}

// ---------------- tiled GEMM 64x128x32, 4x8/thread, double-buffered prefetch ----------------
// C[i,j] = sum_k A[i,k]*B[j,k]; modes as before.
template<int MODE>
__global__ void __launch_bounds__(256) k_gemm(const float* __restrict__ e0,
                                              const float* __restrict__ p0,
                                              const float* __restrict__ p1,
                                              const float* __restrict__ p2,
                                              const float* __restrict__ p3) {
    constexpr int BM = 64, BN = 128, BK = 32;
    constexpr int K = (MODE == 0 || MODE == 1 || MODE == 4) ? 256 :
                      (MODE == 2 ? 2048 : (MODE == 3 ? 512 : 1024));
    int b = blockIdx.z;
    const float* A = nullptr; const float* Bm;
    if constexpr (MODE == 0)      { A = g_Xtp + (size_t)b * NP * CH;  Bm = e0; }
    else if constexpr (MODE == 1) { A = e0;                           Bm = g_Xti + (size_t)b * NP * CH; }
    else if constexpr (MODE == 2) { Bm = g_imf + (size_t)b * CH * NP; }
    else if constexpr (MODE == 3) { A = g_xcat + (size_t)b * NP * 2 * CH; Bm = e0; }
    else if constexpr (MODE == 4) { A = g_x + (size_t)b * NP * CH;    Bm = e0; }
    else                          { A = g_h + (size_t)b * NP * FFNC;  Bm = e0; }

    __shared__ float Asm[BK][BM + 4];
    __shared__ float Bsm[BK][BN + 4];
    int i0 = blockIdx.y * BM, j0 = blockIdx.x * BN;
    int tx = threadIdx.x & 15, ty = threadIdx.x >> 4;
    float acc[4][8];
    #pragma unroll
    for (int r = 0; r < 4; r++)
        #pragma unroll
        for (int c = 0; c < 8; c++) acc[r][c] = 0.f;

    // per-thread load coordinates
    int aI[2], aK[2], bI[4], bK[4];
    #pragma unroll
    for (int s = 0; s < 2; s++) { int f4 = threadIdx.x + s * 256; aI[s] = f4 >> 3; aK[s] = (f4 & 7) * 4; }
    #pragma unroll
    for (int s = 0; s < 4; s++) { int f4 = threadIdx.x + s * 256; bI[s] = f4 >> 3; bK[s] = (f4 & 7) * 4; }
    int a2I = threadIdx.x >> 2, a2K = (threadIdx.x & 3) * 8;   // mode-2 fp16 A

    float4 pa[2]; uint4 pa2; float4 pb[4];

    // prefetch tile 0
    if constexpr (MODE == 2) {
        const __half* Ah = g_Qh + (size_t)b * NP * NP;
        pa2 = *(const uint4*)(Ah + (size_t)(i0 + a2I) * K + a2K);
    } else {
        #pragma unroll
        for (int s = 0; s < 2; s++) pa[s] = *(const float4*)(A + (size_t)(i0 + aI[s]) * K + aK[s]);
    }
    #pragma unroll
    for (int s = 0; s < 4; s++) pb[s] = *(const float4*)(Bm + (size_t)(j0 + bI[s]) * K + bK[s]);

    for (int k0 = 0; k0 < K; k0 += BK) {
        // stage prefetched tile into smem
        if constexpr (MODE == 2) {
            const __half2* ah = (const __half2*)&pa2;
            #pragma unroll
            for (int h = 0; h < 4; h++) {
                float2 af = __half22float2(ah[h]);
                Asm[a2K + 2 * h][a2I] = af.x;
                Asm[a2K + 2 * h + 1][a2I] = af.y;
            }
        } else {
            #pragma unroll
            for (int s = 0; s < 2; s++) {
                Asm[aK[s] + 0][aI[s]] = pa[s].x; Asm[aK[s] + 1][aI[s]] = pa[s].y;
                Asm[aK[s] + 2][aI[s]] = pa[s].z; Asm[aK[s] + 3][aI[s]] = pa[s].w;
            }
        }
        #pragma unroll
        for (int s = 0; s < 4; s++) {
            Bsm[bK[s] + 0][bI[s]] = pb[s].x; Bsm[bK[s] + 1][bI[s]] = pb[s].y;
            Bsm[bK[s] + 2][bI[s]] = pb[s].z; Bsm[bK[s] + 3][bI[s]] = pb[s].w;
        }
        __syncthreads();

        // prefetch next tile (overlaps with compute below)
        int kn = k0 + BK;
        if (kn < K) {
            if constexpr (MODE == 2) {
                const __half* Ah = g_Qh + (size_t)b * NP * NP;
                pa2 = *(const uint4*)(Ah + (size_t)(i0 + a2I) * K + kn + a2K);
            } else {
                #pragma unroll
                for (int s = 0; s < 2; s++) pa[s] = *(const float4*)(A + (size_t)(i0 + aI[s]) * K + kn + aK[s]);
            }
            #pragma unroll
            for (int s = 0; s < 4; s++) pb[s] = *(const float4*)(Bm + (size_t)(j0 + bI[s]) * K + kn + bK[s]);
        }

        #pragma unroll
        for (int kk = 0; kk < BK; kk++) {
            float4 a0 = *(const float4*)&Asm[kk][ty * 4];
            float4 b0 = *(const float4*)&Bsm[kk][tx * 8];
            float4 b1 = *(const float4*)&Bsm[kk][tx * 8 + 4];
            float ar[4] = {a0.x, a0.y, a0.z, a0.w};
            float br[8] = {b0.x, b0.y, b0.z, b0.w, b1.x, b1.y, b1.z, b1.w};
            #pragma unroll
            for (int r = 0; r < 4; r++)
                #pragma unroll
                for (int c = 0; c < 8; c++) acc[r][c] += ar[r] * br[c];
        }
        __syncthreads();
    }

    int j = j0 + tx * 8;
    float bc[8], w0c[8], w1c[8], ppx[8], ppy[8], bvc[8];
    if constexpr (MODE == 0) {
        #pragma unroll
        for (int c = 0; c < 8; c++) {
            bc[c] = p0[j + c] + p1[j + c];
            w0c[c] = p2[2 * (j + c)];
            w1c[c] = p2[2 * (j + c) + 1];
        }
    } else if constexpr (MODE == 1) {
        #pragma unroll
        for (int c = 0; c < 8; c++) {
            float2 pp = ((const float2*)p3)[b * NP + j + c];
            ppx[c] = pp.x; ppy[c] = pp.y;
            bvc[c] = g_bv[b * NP + j + c];
        }
    } else if constexpr (MODE == 3 || MODE == 4 || MODE == 5) {
        #pragma unroll
        for (int c = 0; c < 8; c++) bc[c] = p0[j + c];
    }

    #pragma unroll
    for (int r = 0; r < 4; r++) {
        int i = i0 + ty * 4 + r;
        float vr[8];
        #pragma unroll
        for (int c = 0; c < 8; c++) vr[c] = acc[r][c];
        if constexpr (MODE == 0) {
            float2 pp = ((const float2*)p3)[b * NP + i];
            #pragma unroll
            for (int c = 0; c < 8; c++) vr[c] += bc[c] + w0c[c] * pp.x + w1c[c] * pp.y;
            float* o = g_xcat + ((size_t)(b * NP + i)) * (2 * CH) + j;
            *(float4*)o = make_float4(vr[0], vr[1], vr[2], vr[3]);
            *(float4*)(o + 4) = make_float4(vr[4], vr[5], vr[6], vr[7]);
        } else if constexpr (MODE == 1) {
            float bia = p0[i] + p1[i];
            float w0 = p2[2 * i], w1 = p2[2 * i + 1];
            #pragma unroll
            for (int c = 0; c < 8; c++) vr[c] = (vr[c] + bia + w0 * ppx[c] + w1 * ppy[c]) * bvc[c];
            float* o = g_imf + (size_t)b * CH * NP + (size_t)i * NP + j;
            *(float4*)o = make_float4(vr[0], vr[1], vr[2], vr[3]);
            *(float4*)(o + 4) = make_float4(vr[4], vr[5], vr[6], vr[7]);
        } else if constexpr (MODE == 2) {
            float w = g_wv[b * NP + i];
            #pragma unroll
            for (int c = 0; c < 8; c++) vr[c] *= w;
            float* o = g_xcat + ((size_t)(b * NP + i)) * (2 * CH) + CH + j;
            *(float4*)o = make_float4(vr[0], vr[1], vr[2], vr[3]);
            *(float4*)(o + 4) = make_float4(vr[4], vr[5], vr[6], vr[7]);
        } else if constexpr (MODE == 3) {
            #pragma unroll
            for (int c = 0; c < 8; c++) vr[c] += bc[c];
            float* o = g_x + ((size_t)(b * NP + i)) * CH + j;
            *(float4*)o = make_float4(vr[0], vr[1], vr[2], vr[3]);
            *(float4*)(o + 4) = make_float4(vr[4], vr[5], vr[6], vr[7]);
        } else if constexpr (MODE == 4) {
            #pragma unroll
            for (int c = 0; c < 8; c++) vr[c] = fmaxf(vr[c] + bc[c], 0.f);
            float* o = g_h + ((size_t)(b * NP + i)) * FFNC + j;
            *(float4*)o = make_float4(vr[0], vr[1], vr[2], vr[3]);
            *(float4*)(o + 4) = make_float4(vr[4], vr[5], vr[6], vr[7]);
        } else {
            const float* rsd = g_x + ((size_t)(b * NP + i)) * CH + j;
            float4 r0 = *(const float4*)rsd, r1 = *(const float4*)(rsd + 4);
            vr[0] += bc[0] + r0.x; vr[1] += bc[1] + r0.y; vr[2] += bc[2] + r0.z; vr[3] += bc[3] + r0.w;
            vr[4] += bc[4] + r1.x; vr[5] += bc[5] + r1.y; vr[6] += bc[6] + r1.z; vr[7] += bc[7] + r1.w;
            float* o = g_y2 + ((size_t)(b * NP + i)) * CH + j;
            *(float4*)o = make_float4(vr[0], vr[1], vr[2], vr[3]);
            *(float4*)(o + 4) = make_float4(vr[4], vr[5], vr[6], vr[7]);
        }
    }
}

// ---------------- LayerNorm in place on g_x ----------------
__global__ void k_ln(const float* __restrict__ gamma, const float* __restrict__ beta) {
    int row = blockIdx.x * 8 + (threadIdx.x >> 5);
    int lane = threadIdx.x & 31;
    float* x = g_x + (size_t)row * CH + lane * 8;
    float4 v0 = *(float4*)x;
    float4 v1 = *(float4*)(x + 4);
    float s = v0.x + v0.y + v0.z + v0.w + v1.x + v1.y + v1.z + v1.w;
    float s2 = v0.x * v0.x + v0.y * v0.y + v0.z * v0.z + v0.w * v0.w +
               v1.x * v1.x + v1.y * v1.y + v1.z * v1.z + v1.w * v1.w;
    #pragma unroll
    for (int o = 16; o; o >>= 1) {
        s  += __shfl_xor_sync(0xffffffffu, s, o);
        s2 += __shfl_xor_sync(0xffffffffu, s2, o);
    }
    float mu = s * (1.f / CH);
    float var = s2 * (1.f / CH) - mu * mu;
    float inv = rsqrtf(var + 1e-5f);
    int c = lane * 8;
    float4 g0 = *(const float4*)(gamma + c), g1 = *(const float4*)(gamma + c + 4);
    float4 b0 = *(const float4*)(beta + c),  b1 = *(const float4*)(beta + c + 4);
    v0.x = (v0.x - mu) * inv * g0.x + b0.x; v0.y = (v0.y - mu) * inv * g0.y + b0.y;
    v0.z = (v0.z - mu) * inv * g0.z + b0.z; v0.w = (v0.w - mu) * inv * g0.w + b0.w;
    v1.x = (v1.x - mu) * inv * g1.x + b1.x; v1.y = (v1.y - mu) * inv * g1.y + b1.y;
    v1.z = (v1.z - mu) * inv * g1.z + b1.z; v1.w = (v1.w - mu) * inv * g1.w + b1.w;
    *(float4*)x = v0;
    *(float4*)(x + 4) = v1;
}

// ---------------- final LN + prediction head + outputs ----------------
__global__ void k_final(const float* __restrict__ gamma, const float* __restrict__ beta,
                        const float* __restrict__ Wpred, const float* __restrict__ bpred,
                        const float* __restrict__ ppos,
                        float* __restrict__ out_x, float* __restrict__ out_np,
                        float* __restrict__ out_c) {
    int row = blockIdx.x * 8 + (threadIdx.x >> 5);
    int lane = threadIdx.x & 31;
    int b = row >> 11, n = row & (NP - 1);
    const float* y = g_y2 + (size_t)row * CH + lane * 8;
    float4 v0 = *(const float4*)y;
    float4 v1 = *(const float4*)(y + 4);
    float s = v0.x + v0.y + v0.z + v0.w + v1.x + v1.y + v1.z + v1.w;
    float s2 = v0.x * v0.x + v0.y * v0.y + v0.z * v0.z + v0.w * v0.w +
               v1.x * v1.x + v1.y * v1.y + v1.z * v1.z + v1.w * v1.w;
    #pragma unroll
    for (int o = 16; o; o >>= 1) {
        s  += __shfl_xor_sync(0xffffffffu, s, o);
        s2 += __shfl_xor_sync(0xffffffffu, s2, o);
    }
    float mu = s * (1.f / CH);
    float var = s2 * (1.f / CH) - mu * mu;
    float inv = rsqrtf(var + 1e-5f);
    int c = lane * 8;
    float4 g0 = *(const float4*)(gamma + c), g1 = *(const float4*)(gamma + c + 4);
    float4 b0 = *(const float4*)(beta + c),  b1 = *(const float4*)(beta + c + 4);
    v0.x = (v0.x - mu) * inv * g0.x + b0.x; v0.y = (v0.y - mu) * inv * g0.y + b0.y;
    v0.z = (v0.z - mu) * inv * g0.z + b0.z; v0.w = (v0.w - mu) * inv * g0.w + b0.w;
    v1.x = (v1.x - mu) * inv * g1.x + b1.x; v1.y = (v1.y - mu) * inv * g1.y + b1.y;
    v1.z = (v1.z - mu) * inv * g1.z + b1.z; v1.w = (v1.w - mu) * inv * g1.w + b1.w;

    float4 w00 = *(const float4*)(Wpred + c),      float4_w01 = {0,0,0,0};
    float4 w01 = *(const float4*)(Wpred + c + 4);
    float4 w10 = *(const float4*)(Wpred + CH + c), w11 = *(const float4*)(Wpred + CH + c + 4);
    float d0 = v0.x * w00.x + v0.y * w00.y + v0.z * w00.z + v0.w * w00.w +
               v1.x * w01.x + v1.y * w01.y + v1.z * w01.z + v1.w * w01.w;
    float d1 = v0.x * w10.x + v0.y * w10.y + v0.z * w10.z + v0.w * w10.w +
               v1.x * w11.x + v1.y * w11.y + v1.z * w11.z + v1.w * w11.w;
    (void)float4_w01;
    #pragma unroll
    for (int o = 16; o; o >>= 1) {
        d0 += __shfl_xor_sync(0xffffffffu, d0, o);
        d1 += __shfl_xor_sync(0xffffffffu, d1, o);
    }
    float* ox = out_x + (size_t)b * CH * NP + n;
    ox[(size_t)(c + 0) * NP] = v0.x; ox[(size_t)(c + 1) * NP] = v0.y;
    ox[(size_t)(c + 2) * NP] = v0.z; ox[(size_t)(c + 3) * NP] = v0.w;
    ox[(size_t)(c + 4) * NP] = v1.x; ox[(size_t)(c + 5) * NP] = v1.y;
    ox[(size_t)(c + 6) * NP] = v1.z; ox[(size_t)(c + 7) * NP] = v1.w;
    if (lane == 0) {
        float2 pp = ((const float2*)ppos)[b * NP + n];
        float c0 = d0 + bpred[0] + pp.x;
        float c1 = d1 + bpred[1] + pp.y;
        out_c[(size_t)b * 2 * NP + n] = c0;
        out_c[(size_t)b * 2 * NP + NP + n] = c1;
        ((float2*)out_np)[b * NP + n] = make_float2(c0, c1);
    }
}

// ---------------- launch ----------------
extern "C" void kernel_launch(void* const* d_in, const int* in_sizes, int n_in,
                              void* d_out, int out_size) {
    const float* ptsf   = (const float*)d_in[0];
    const float* ppos   = (const float*)d_in[1];
    const float* imgf   = (const float*)d_in[2];
    const float* ipos   = (const float*)d_in[3];
    const float* ptscls = (const float*)d_in[4];
    const float* imgcls = (const float*)d_in[5];
    const float* Wp  = (const float*)d_in[6];  const float* bp  = (const float*)d_in[7];
    const float* Wi  = (const float*)d_in[8];  const float* bi  = (const float*)d_in[9];
    const float* Wqp = (const float*)d_in[10]; const float* bqp = (const float*)d_in[11];
    const float* Wkp = (const float*)d_in[12]; const float* bkp = (const float*)d_in[13];
    const float* Wout = (const float*)d_in[14]; const float* bout = (const float*)d_in[15];
    const float* gout = (const float*)d_in[16]; const float* betaout = (const float*)d_in[17];
    const float* Wf1 = (const float*)d_in[18]; const float* bf1 = (const float*)d_in[19];
    const float* Wf2 = (const float*)d_in[20]; const float* bf2 = (const float*)d_in[21];
    const float* gln = (const float*)d_in[22]; const float* bln = (const float*)d_in[23];
    const float* Wpred = (const float*)d_in[24]; const float* bpred = (const float*)d_in[25];

    float* out    = (float*)d_out;
    float* out_x  = out;                                   // [2,256,2048]
    float* out_np = out + (size_t)BSZ * CH * NP;           // [2,2048,2]
    float* out_c  = out_np + (size_t)BSZ * NP * 2;         // [2,2,2048]

    const int IPOT_SMEM = NP * (int)sizeof(float) + 8 * NP * (int)sizeof(__half);  // 40 KB
    cudaFuncSetAttribute(k_ipot_persist, cudaFuncAttributeMaxDynamicSharedMemorySize, IPOT_SMEM);

    dim3 tb(32, 8);
    k_cls<<<NROW / 256, 256>>>(ptscls, imgcls);                    // launch 1
    k_transpose<<<dim3(NP / 32, CH / 32, BSZ), tb>>>(ptsf, 0);     // launch 2
    k_transpose<<<dim3(NP / 32, CH / 32, BSZ), tb>>>(imgf, 1);     // launch 3

    // launch 4 (ncu capture slot): ALL 100 IPOT iterations (R8 structure)
    k_ipot_persist<<<NBLK, 256, IPOT_SMEM>>>(ppos, ipos);

    // projections + positional embeddings
    k_gemm<0><<<dim3(CH / 128, NP / 64, BSZ), 256>>>(Wp, bp, bqp, Wqp, ppos);
    k_gemm<1><<<dim3(NP / 128, CH / 64, BSZ), 256>>>(Wi, bi, bkp, Wkp, ipos);  // *bv folded

    // attention GEMM: img_att = w ⊙ (Q_fp16 @ imf_scaled^T)
    k_gemm<2><<<dim3(CH / 128, NP / 64, BSZ), 256>>>(nullptr, nullptr, nullptr, nullptr, nullptr);
    // out projection + LN
    k_gemm<3><<<dim3(CH / 128, NP / 64, BSZ), 256>>>(Wout, bout, nullptr, nullptr, nullptr);
    k_ln<<<NROW / 8, 256>>>(gout, betaout);
    // FFN
    k_gemm<4><<<dim3(FFNC / 128, NP / 64, BSZ), 256>>>(Wf1, bf1, nullptr, nullptr, nullptr);
    k_gemm<5><<<dim3(CH / 128, NP / 64, BSZ), 256>>>(Wf2, bf2, nullptr, nullptr, nullptr);
    // final LN + head + outputs
    k_final<<<NROW / 8, 256>>>(gln, bln, Wpred, bpred, ppos, out_x, out_np, out_c);
}

// round 14
// speedup vs baseline: 1.1145x; 1.0391x over previous
#include <cuda_runtime.h>
#include <cuda_fp16.h>
#include <stdint.h>
#include <math.h>

#define BSZ 2
#define NP  2048
#define CH  256
#define FFNC 1024
#define NROW (BSZ*NP)
#define NBLK 256           // persistent IPOT grid (128 per batch, 16 rows each)

// ---------------- scratch (device globals; no allocations) ----------------
__device__ __half g_Qh[(size_t)BSZ*NP*NP];   // IPOT transport matrix (fp16), in place
__device__ __half g_Gh[(size_t)BSZ*NP*NP];   // exp(-cost/10) (fp16)
__device__ float g_Xtp[(size_t)BSZ*NP*CH];   // pts feat transposed [b,n,c]
__device__ float g_Xti[(size_t)BSZ*NP*CH];   // img feat transposed [b,n,c]
__device__ float g_imf[(size_t)BSZ*CH*NP];   // img projected feat [b,c,m] (pre-scaled by b)
__device__ float g_xcat[(size_t)BSZ*NP*2*CH];// [pf ; img_att] token-major [b,n,512]
__device__ float g_x[(size_t)BSZ*NP*CH];     // post out-proj (+LN in place)
__device__ float g_h[(size_t)BSZ*NP*FFNC];   // FFN hidden
__device__ float g_y2[(size_t)BSZ*NP*CH];    // FFN out + residual
__device__ float g_pcls[NROW], g_icls[NROW];
__device__ float g_bv[NROW], g_wv[NROW];
__device__ float g_v[3][NROW];               // triple-buffered column sums v = Q^T a

// per-batch grid-barrier state (zero-initialized; generations monotonic across replays)
__device__ unsigned g_cnt2[2][8];
__device__ unsigned g_cntm2[2];
__device__ volatile unsigned g_gen2[2];

// ---------------- per-batch software grid barrier (128 co-resident blocks) ----------------
__device__ __forceinline__ void gridbar(int batch, int lb) {
    __syncthreads();
    if (threadIdx.x == 0) {
        unsigned my = g_gen2[batch];
        __threadfence();
        unsigned s = lb & 7;                         // 8 groups of 16
        if (atomicAdd(&g_cnt2[batch][s], 1) == 15) {
            g_cnt2[batch][s] = 0;
            if (atomicAdd(&g_cntm2[batch], 1) == 7) {
                g_cntm2[batch] = 0;
                __threadfence();
                g_gen2[batch] = my + 1;
            }
        }
        while (g_gen2[batch] == my) { __nanosleep(32); }
        __threadfence();
    }
    __syncthreads();
}

// ---------------- transpose [b,C,N] -> [b,N,C] ----------------
__global__ void k_transpose(const float* __restrict__ src, int which) {
    __shared__ float t[32][33];
    int b = blockIdx.z;
    float* dst = which ? g_Xti : g_Xtp;
    const float* s = src + (size_t)b * CH * NP;
    float* d = dst + (size_t)b * NP * CH;
    int n0 = blockIdx.x * 32, c0 = blockIdx.y * 32;
    for (int i = threadIdx.y; i < 32; i += 8)
        t[i][threadIdx.x] = s[(size_t)(c0 + i) * NP + n0 + threadIdx.x];
    __syncthreads();
    for (int i = threadIdx.y; i < 32; i += 8)
        d[(size_t)(n0 + i) * CH + c0 + threadIdx.x] = t[threadIdx.x][i];
}

// ---------------- pcls/icls = sigmoid(max over classes) ----------------
__global__ void k_cls(const float* __restrict__ pc, const float* __restrict__ ic) {
    int idx = blockIdx.x * 256 + threadIdx.x;   // 0..4095
    int b = idx >> 11, n = idx & (NP - 1);
    const float* p = pc + (size_t)b * 10 * NP + n;
    const float* q = ic + (size_t)b * 10 * NP + n;
    float mp = -1e30f, mi = -1e30f;
    #pragma unroll
    for (int c = 0; c < 10; c++) {
        mp = fmaxf(mp, p[(size_t)c * NP]);
        mi = fmaxf(mi, q[(size_t)c * NP]);
    }
    g_pcls[idx] = 1.f / (1.f + expf(-mp));
    g_icls[idx] = 1.f / (1.f + expf(-mi));
}

// ---------------- persistent IPOT (R8 core; per-batch barriers; vector b-phase) ----------------
__global__ void __launch_bounds__(256, 2) k_ipot_persist(
    const float* __restrict__ ppos, const float* __restrict__ ipos) {
    extern __shared__ float sm[];         // 8KB fp32 b + 32KB fp16 slots = 40KB
    float* sh_b = sm;
    __half* sh_ph = (__half*)(sm + NP);
    int tid = threadIdx.x, lane = tid & 31, wid = tid >> 5;
    int bid = blockIdx.x;
    int batch = bid >> 7, lb = bid & 127;
    int boff = batch * NP;
    int row0 = lb * 16;

    float pc0 = g_pcls[boff + row0 + wid];
    float pc1 = g_pcls[boff + row0 + wid + 8];
    float an_keep[2];
    an_keep[0] = 0.f; an_keep[1] = 0.f;

    // icls for this thread's 8 b-columns, cached in registers
    float icz[8];
    {
        float4 i0 = *(const float4*)(g_icls + boff + tid * 8);
        float4 i1 = *(const float4*)(g_icls + boff + tid * 8 + 4);
        icz[0]=i0.x; icz[1]=i0.y; icz[2]=i0.z; icz[3]=i0.w;
        icz[4]=i1.x; icz[5]=i1.y; icz[6]=i1.z; icz[7]=i1.w;
    }

    // prologue: zero v[1] (t=1 accumulation target); idempotent across blocks
    {
        float4 z = make_float4(0.f, 0.f, 0.f, 0.f);
        float* vz = g_v[1] + boff + tid * 8;
        *(float4*)vz = z; *(float4*)(vz + 4) = z;
    }
    gridbar(batch, lb);

    for (int t = 1; t <= 100; t++) {
        // b into smem (t>1), vectorized; zero v[(t+1)%3]
        {
            float4 z = make_float4(0.f, 0.f, 0.f, 0.f);
            float* vz = g_v[(t + 1) % 3] + boff + tid * 8;
            if (t > 1) {
                const float4* vr = (const float4*)(g_v[(t - 1) % 3] + boff + tid * 8);
                float4 v0 = __ldcg(vr), v1 = __ldcg(vr + 1);
                float4 b0, b1;
                b0.x = __fdividef(icz[0], v0.x + 1e-6f);
                b0.y = __fdividef(icz[1], v0.y + 1e-6f);
                b0.z = __fdividef(icz[2], v0.z + 1e-6f);
                b0.w = __fdividef(icz[3], v0.w + 1e-6f);
                b1.x = __fdividef(icz[4], v1.x + 1e-6f);
                b1.y = __fdividef(icz[5], v1.y + 1e-6f);
                b1.z = __fdividef(icz[6], v1.z + 1e-6f);
                b1.w = __fdividef(icz[7], v1.w + 1e-6f);
                *(float4*)(sh_b + tid * 8) = b0;
                *(float4*)(sh_b + tid * 8 + 4) = b1;
            }
            *(float4*)vz = z; *(float4*)(vz + 4) = z;
        }
        __syncthreads();

        __half* pwh = sh_ph + wid * NP;
        #pragma unroll
        for (int rr = 0; rr < 2; rr++) {
            int row = row0 + wid + rr * 8;
            size_t base = (size_t)(boff + row) * NP;
            float qv[8][8];
            float u = 0.f;

            if (t == 1) {
                float2 pp = ((const float2*)ppos)[boff + row];
                const float2* ip = (const float2*)ipos + boff;
                #pragma unroll
                for (int j = 0; j < 8; j++) {
                    int c = (j * 32 + lane) * 8;
                    float qn[8];
                    #pragma unroll
                    for (int h = 0; h < 8; h++) {
                        float2 q2 = ip[c + h];
                        float dx = pp.x - q2.x, dy = pp.y - q2.y;
                        qn[h] = expf(-0.1f * sqrtf(dx * dx + dy * dy));
                    }
                    uint4 go; __half2* goh = (__half2*)&go;
                    uint4 qo; __half2* qoh = (__half2*)&qo;
                    #pragma unroll
                    for (int h = 0; h < 4; h++) {
                        goh[h] = __floats2half2_rn(qn[2 * h], qn[2 * h + 1]);
                        float a0 = fmaxf(qn[2 * h], 1e-6f), a1 = fmaxf(qn[2 * h + 1], 1e-6f);
                        qoh[h] = __floats2half2_rn(a0, a1);
                        qv[j][2 * h] = a0; qv[j][2 * h + 1] = a1;
                        u += a0 + a1;
                    }
                    *(uint4*)(g_Gh + base + c) = go;
                    *(uint4*)(g_Qh + base + c) = qo;
                }
                u *= (1.0f / NP);
            } else {
                float ap = an_keep[rr];
                #pragma unroll
                for (int j = 0; j < 8; j++) {
                    int c = (j * 32 + lane) * 8;
                    uint4 gq = *(const uint4*)(g_Gh + base + c);
                    uint4 qq = *(const uint4*)(g_Qh + base + c);
                    const __half2* gh = (const __half2*)&gq;
                    const __half2* qh = (const __half2*)&qq;
                    float4 b0 = *(const float4*)(sh_b + c);
                    float4 b1 = *(const float4*)(sh_b + c + 4);
                    float bb[8] = {b0.x, b0.y, b0.z, b0.w, b1.x, b1.y, b1.z, b1.w};
                    uint4 qo; __half2* qoh = (__half2*)&qo;
                    #pragma unroll
                    for (int h = 0; h < 4; h++) {
                        float2 gf = __half22float2(gh[h]);
                        float2 qf = __half22float2(qh[h]);
                        float n0 = fmaxf(gf.x * (ap * qf.x * bb[2 * h]), 1e-6f);
                        float n1 = fmaxf(gf.y * (ap * qf.y * bb[2 * h + 1]), 1e-6f);
                        qoh[h] = __floats2half2_rn(n0, n1);
                        qv[j][2 * h] = n0; qv[j][2 * h + 1] = n1;
                        u += n0 * bb[2 * h] + n1 * bb[2 * h + 1];
                    }
                    *(uint4*)(g_Qh + base + c) = qo;
                }
            }
            #pragma unroll
            for (int o = 16; o; o >>= 1) u += __shfl_xor_sync(0xffffffffu, u, o);
            float an = __fdividef((rr == 0 ? pc0 : pc1), u + 1e-6f);
            an_keep[rr] = an;

            if (rr == 0) {
                #pragma unroll
                for (int j = 0; j < 8; j++) {
                    int c = (j * 32 + lane) * 8;
                    uint4 st; __half2* sth = (__half2*)&st;
                    #pragma unroll
                    for (int h = 0; h < 4; h++)
                        sth[h] = __floats2half2_rn(an * qv[j][2 * h], an * qv[j][2 * h + 1]);
                    *(uint4*)(pwh + c) = st;
                }
            } else {
                #pragma unroll
                for (int j = 0; j < 8; j++) {
                    int c = (j * 32 + lane) * 8;
                    uint4 old = *(uint4*)(pwh + c);
                    __half2* oh = (__half2*)&old;
                    uint4 st; __half2* sth = (__half2*)&st;
                    #pragma unroll
                    for (int h = 0; h < 4; h++) {
                        float2 f = __half22float2(oh[h]);
                        sth[h] = __floats2half2_rn(f.x + an * qv[j][2 * h],
                                                   f.y + an * qv[j][2 * h + 1]);
                    }
                    *(uint4*)(pwh + c) = st;
                }
            }
        }
        __syncthreads();

        float* vw = g_v[t % 3] + boff;
        #pragma unroll
        for (int jj = 0; jj < 4; jj++) {
            int m = 2 * tid + 512 * jj;
            float s0 = 0.f, s1 = 0.f;
            #pragma unroll
            for (int w = 0; w < 8; w++) {
                __half2 hv = *(const __half2*)(sh_ph + w * NP + m);
                float2 f = __half22float2(hv);
                s0 += f.x; s1 += f.y;
            }
            atomicAdd(vw + m, s0);
            atomicAdd(vw + m + 1, s1);
        }
        gridbar(batch, lb);
    }

    // epilogue: b_final -> smem (+ g_bv once per batch)
    {
        const float4* vf = (const float4*)(g_v[1] + boff + tid * 8);
        float4 v0 = __ldcg(vf), v1 = __ldcg(vf + 1);
        float4 b0, b1;
        b0.x = __fdividef(icz[0], v0.x + 1e-6f);
        b0.y = __fdividef(icz[1], v0.y + 1e-6f);
        b0.z = __fdividef(icz[2], v0.z + 1e-6f);
        b0.w = __fdividef(icz[3], v0.w + 1e-6f);
        b1.x = __fdividef(icz[4], v1.x + 1e-6f);
        b1.y = __fdividef(icz[5], v1.y + 1e-6f);
        b1.z = __fdividef(icz[6], v1.z + 1e-6f);
        b1.w = __fdividef(icz[7], v1.w + 1e-6f);
        *(float4*)(sh_b + tid * 8) = b0;
        *(float4*)(sh_b + tid * 8 + 4) = b1;
        if (lb == 0) {
            *(float4*)(g_bv + boff + tid * 8) = b0;
            *(float4*)(g_bv + boff + tid * 8 + 4) = b1;
        }
    }
    __syncthreads();

    // row-normalization scale
    #pragma unroll
    for (int rr = 0; rr < 2; rr++) {
        int row = row0 + wid + rr * 8;
        size_t base = (size_t)(boff + row) * NP;
        float srs = 0.f;
        #pragma unroll
        for (int j = 0; j < 8; j++) {
            int c = (j * 32 + lane) * 8;
            uint4 qq = *(const uint4*)(g_Qh + base + c);
            const __half2* qh = (const __half2*)&qq;
            float4 b0 = *(const float4*)(sh_b + c);
            float4 b1 = *(const float4*)(sh_b + c + 4);
            float bb[8] = {b0.x, b0.y, b0.z, b0.w, b1.x, b1.y, b1.z, b1.w};
            #pragma unroll
            for (int h = 0; h < 4; h++) {
                float2 qf = __half22float2(qh[h]);
                srs += qf.x * bb[2 * h] + qf.y * bb[2 * h + 1];
            }
        }
        #pragma unroll
        for (int o = 16; o; o >>= 1) srs += __shfl_xor_sync(0xffffffffu, srs, o);
        if (lane == 0) {
            float a = an_keep[rr];
            g_wv[boff + row] = a / fmaxf(a * srs, 1e-12f);
        }
    }
}

// ---------------- tiled GEMM 64x128x32, 4x8/thread, double-buffered prefetch ----------------
template<int MODE>
__global__ void __launch_bounds__(256) k_gemm(const float* __restrict__ e0,
                                              const float* __restrict__ p0,
                                              const float* __restrict__ p1,
                                              const float* __restrict__ p2,
                                              const float* __restrict__ p3) {
    constexpr int BM = 64, BN = 128, BK = 32;
    constexpr int K = (MODE == 0 || MODE == 1 || MODE == 4) ? 256 :
                      (MODE == 2 ? 2048 : (MODE == 3 ? 512 : 1024));
    int b = blockIdx.z;
    const float* A = nullptr; const float* Bm;
    if constexpr (MODE == 0)      { A = g_Xtp + (size_t)b * NP * CH;  Bm = e0; }
    else if constexpr (MODE == 1) { A = e0;                           Bm = g_Xti + (size_t)b * NP * CH; }
    else if constexpr (MODE == 2) { Bm = g_imf + (size_t)b * CH * NP; }
    else if constexpr (MODE == 3) { A = g_xcat + (size_t)b * NP * 2 * CH; Bm = e0; }
    else if constexpr (MODE == 4) { A = g_x + (size_t)b * NP * CH;    Bm = e0; }
    else                          { A = g_h + (size_t)b * NP * FFNC;  Bm = e0; }

    __shared__ float Asm[BK][BM + 4];
    __shared__ float Bsm[BK][BN + 4];
    int i0 = blockIdx.y * BM, j0 = blockIdx.x * BN;
    int tx = threadIdx.x & 15, ty = threadIdx.x >> 4;
    float acc[4][8];
    #pragma unroll
    for (int r = 0; r < 4; r++)
        #pragma unroll
        for (int c = 0; c < 8; c++) acc[r][c] = 0.f;

    int aI[2], aK[2], bI[4], bK[4];
    #pragma unroll
    for (int s = 0; s < 2; s++) { int f4 = threadIdx.x + s * 256; aI[s] = f4 >> 3; aK[s] = (f4 & 7) * 4; }
    #pragma unroll
    for (int s = 0; s < 4; s++) { int f4 = threadIdx.x + s * 256; bI[s] = f4 >> 3; bK[s] = (f4 & 7) * 4; }
    int a2I = threadIdx.x >> 2, a2K = (threadIdx.x & 3) * 8;

    float4 pa[2]; uint4 pa2; float4 pb[4];

    if constexpr (MODE == 2) {
        const __half* Ah = g_Qh + (size_t)b * NP * NP;
        pa2 = *(const uint4*)(Ah + (size_t)(i0 + a2I) * K + a2K);
    } else {
        #pragma unroll
        for (int s = 0; s < 2; s++) pa[s] = *(const float4*)(A + (size_t)(i0 + aI[s]) * K + aK[s]);
    }
    #pragma unroll
    for (int s = 0; s < 4; s++) pb[s] = *(const float4*)(Bm + (size_t)(j0 + bI[s]) * K + bK[s]);

    for (int k0 = 0; k0 < K; k0 += BK) {
        if constexpr (MODE == 2) {
            const __half2* ah = (const __half2*)&pa2;
            #pragma unroll
            for (int h = 0; h < 4; h++) {
                float2 af = __half22float2(ah[h]);
                Asm[a2K + 2 * h][a2I] = af.x;
                Asm[a2K + 2 * h + 1][a2I] = af.y;
            }
        } else {
            #pragma unroll
            for (int s = 0; s < 2; s++) {
                Asm[aK[s] + 0][aI[s]] = pa[s].x; Asm[aK[s] + 1][aI[s]] = pa[s].y;
                Asm[aK[s] + 2][aI[s]] = pa[s].z; Asm[aK[s] + 3][aI[s]] = pa[s].w;
            }
        }
        #pragma unroll
        for (int s = 0; s < 4; s++) {
            Bsm[bK[s] + 0][bI[s]] = pb[s].x; Bsm[bK[s] + 1][bI[s]] = pb[s].y;
            Bsm[bK[s] + 2][bI[s]] = pb[s].z; Bsm[bK[s] + 3][bI[s]] = pb[s].w;
        }
        __syncthreads();

        int kn = k0 + BK;
        if (kn < K) {
            if constexpr (MODE == 2) {
                const __half* Ah = g_Qh + (size_t)b * NP * NP;
                pa2 = *(const uint4*)(Ah + (size_t)(i0 + a2I) * K + kn + a2K);
            } else {
                #pragma unroll
                for (int s = 0; s < 2; s++) pa[s] = *(const float4*)(A + (size_t)(i0 + aI[s]) * K + kn + aK[s]);
            }
            #pragma unroll
            for (int s = 0; s < 4; s++) pb[s] = *(const float4*)(Bm + (size_t)(j0 + bI[s]) * K + kn + bK[s]);
        }

        #pragma unroll
        for (int kk = 0; kk < BK; kk++) {
            float4 a0 = *(const float4*)&Asm[kk][ty * 4];
            float4 b0 = *(const float4*)&Bsm[kk][tx * 8];
            float4 b1 = *(const float4*)&Bsm[kk][tx * 8 + 4];
            float ar[4] = {a0.x, a0.y, a0.z, a0.w};
            float br[8] = {b0.x, b0.y, b0.z, b0.w, b1.x, b1.y, b1.z, b1.w};
            #pragma unroll
            for (int r = 0; r < 4; r++)
                #pragma unroll
                for (int c = 0; c < 8; c++) acc[r][c] += ar[r] * br[c];
        }
        __syncthreads();
    }

    int j = j0 + tx * 8;
    float bc[8], w0c[8], w1c[8], ppx[8], ppy[8], bvc[8];
    if constexpr (MODE == 0) {
        #pragma unroll
        for (int c = 0; c < 8; c++) {
            bc[c] = p0[j + c] + p1[j + c];
            w0c[c] = p2[2 * (j + c)];
            w1c[c] = p2[2 * (j + c) + 1];
        }
    } else if constexpr (MODE == 1) {
        #pragma unroll
        for (int c = 0; c < 8; c++) {
            float2 pp = ((const float2*)p3)[b * NP + j + c];
            ppx[c] = pp.x; ppy[c] = pp.y;
            bvc[c] = g_bv[b * NP + j + c];
        }
    } else if constexpr (MODE == 3 || MODE == 4 || MODE == 5) {
        #pragma unroll
        for (int c = 0; c < 8; c++) bc[c] = p0[j + c];
    }

    #pragma unroll
    for (int r = 0; r < 4; r++) {
        int i = i0 + ty * 4 + r;
        float vr[8];
        #pragma unroll
        for (int c = 0; c < 8; c++) vr[c] = acc[r][c];
        if constexpr (MODE == 0) {
            float2 pp = ((const float2*)p3)[b * NP + i];
            #pragma unroll
            for (int c = 0; c < 8; c++) vr[c] += bc[c] + w0c[c] * pp.x + w1c[c] * pp.y;
            float* o = g_xcat + ((size_t)(b * NP + i)) * (2 * CH) + j;
            *(float4*)o = make_float4(vr[0], vr[1], vr[2], vr[3]);
            *(float4*)(o + 4) = make_float4(vr[4], vr[5], vr[6], vr[7]);
        } else if constexpr (MODE == 1) {
            float bia = p0[i] + p1[i];
            float w0 = p2[2 * i], w1 = p2[2 * i + 1];
            #pragma unroll
            for (int c = 0; c < 8; c++) vr[c] = (vr[c] + bia + w0 * ppx[c] + w1 * ppy[c]) * bvc[c];
            float* o = g_imf + (size_t)b * CH * NP + (size_t)i * NP + j;
            *(float4*)o = make_float4(vr[0], vr[1], vr[2], vr[3]);
            *(float4*)(o + 4) = make_float4(vr[4], vr[5], vr[6], vr[7]);
        } else if constexpr (MODE == 2) {
            float w = g_wv[b * NP + i];
            #pragma unroll
            for (int c = 0; c < 8; c++) vr[c] *= w;
            float* o = g_xcat + ((size_t)(b * NP + i)) * (2 * CH) + CH + j;
            *(float4*)o = make_float4(vr[0], vr[1], vr[2], vr[3]);
            *(float4*)(o + 4) = make_float4(vr[4], vr[5], vr[6], vr[7]);
        } else if constexpr (MODE == 3) {
            #pragma unroll
            for (int c = 0; c < 8; c++) vr[c] += bc[c];
            float* o = g_x + ((size_t)(b * NP + i)) * CH + j;
            *(float4*)o = make_float4(vr[0], vr[1], vr[2], vr[3]);
            *(float4*)(o + 4) = make_float4(vr[4], vr[5], vr[6], vr[7]);
        } else if constexpr (MODE == 4) {
            #pragma unroll
            for (int c = 0; c < 8; c++) vr[c] = fmaxf(vr[c] + bc[c], 0.f);
            float* o = g_h + ((size_t)(b * NP + i)) * FFNC + j;
            *(float4*)o = make_float4(vr[0], vr[1], vr[2], vr[3]);
            *(float4*)(o + 4) = make_float4(vr[4], vr[5], vr[6], vr[7]);
        } else {
            const float* rsd = g_x + ((size_t)(b * NP + i)) * CH + j;
            float4 r0 = *(const float4*)rsd, r1 = *(const float4*)(rsd + 4);
            vr[0] += bc[0] + r0.x; vr[1] += bc[1] + r0.y; vr[2] += bc[2] + r0.z; vr[3] += bc[3] + r0.w;
            vr[4] += bc[4] + r1.x; vr[5] += bc[5] + r1.y; vr[6] += bc[6] + r1.z; vr[7] += bc[7] + r1.w;
            float* o = g_y2 + ((size_t)(b * NP + i)) * CH + j;
            *(float4*)o = make_float4(vr[0], vr[1], vr[2], vr[3]);
            *(float4*)(o + 4) = make_float4(vr[4], vr[5], vr[6], vr[7]);
        }
    }
}

// ---------------- LayerNorm in place on g_x ----------------
__global__ void k_ln(const float* __restrict__ gamma, const float* __restrict__ beta) {
    int row = blockIdx.x * 8 + (threadIdx.x >> 5);
    int lane = threadIdx.x & 31;
    float* x = g_x + (size_t)row * CH + lane * 8;
    float4 v0 = *(float4*)x;
    float4 v1 = *(float4*)(x + 4);
    float s = v0.x + v0.y + v0.z + v0.w + v1.x + v1.y + v1.z + v1.w;
    float s2 = v0.x * v0.x + v0.y * v0.y + v0.z * v0.z + v0.w * v0.w +
               v1.x * v1.x + v1.y * v1.y + v1.z * v1.z + v1.w * v1.w;
    #pragma unroll
    for (int o = 16; o; o >>= 1) {
        s  += __shfl_xor_sync(0xffffffffu, s, o);
        s2 += __shfl_xor_sync(0xffffffffu, s2, o);
    }
    float mu = s * (1.f / CH);
    float var = s2 * (1.f / CH) - mu * mu;
    float inv = rsqrtf(var + 1e-5f);
    int c = lane * 8;
    float4 g0 = *(const float4*)(gamma + c), g1 = *(const float4*)(gamma + c + 4);
    float4 b0 = *(const float4*)(beta + c),  b1 = *(const float4*)(beta + c + 4);
    v0.x = (v0.x - mu) * inv * g0.x + b0.x; v0.y = (v0.y - mu) * inv * g0.y + b0.y;
    v0.z = (v0.z - mu) * inv * g0.z + b0.z; v0.w = (v0.w - mu) * inv * g0.w + b0.w;
    v1.x = (v1.x - mu) * inv * g1.x + b1.x; v1.y = (v1.y - mu) * inv * g1.y + b1.y;
    v1.z = (v1.z - mu) * inv * g1.z + b1.z; v1.w = (v1.w - mu) * inv * g1.w + b1.w;
    *(float4*)x = v0;
    *(float4*)(x + 4) = v1;
}

// ---------------- final LN + prediction head + coalesced outputs ----------------
__global__ void k_final(const float* __restrict__ gamma, const float* __restrict__ beta,
                        const float* __restrict__ Wpred, const float* __restrict__ bpred,
                        const float* __restrict__ ppos,
                        float* __restrict__ out_x, float* __restrict__ out_np,
                        float* __restrict__ out_c) {
    __shared__ float tile[8][260];
    int tid = threadIdx.x;
    int row = blockIdx.x * 8 + (tid >> 5);
    int lane = tid & 31;
    int wid = tid >> 5;
    int b = row >> 11, n = row & (NP - 1);
    const float* y = g_y2 + (size_t)row * CH + lane * 8;
    float4 v0 = *(const float4*)y;
    float4 v1 = *(const float4*)(y + 4);
    float s = v0.x + v0.y + v0.z + v0.w + v1.x + v1.y + v1.z + v1.w;
    float s2 = v0.x * v0.x + v0.y * v0.y + v0.z * v0.z + v0.w * v0.w +
               v1.x * v1.x + v1.y * v1.y + v1.z * v1.z + v1.w * v1.w;
    #pragma unroll
    for (int o = 16; o; o >>= 1) {
        s  += __shfl_xor_sync(0xffffffffu, s, o);
        s2 += __shfl_xor_sync(0xffffffffu, s2, o);
    }
    float mu = s * (1.f / CH);
    float var = s2 * (1.f / CH) - mu * mu;
    float inv = rsqrtf(var + 1e-5f);
    int c = lane * 8;
    float4 g0 = *(const float4*)(gamma + c), g1 = *(const float4*)(gamma + c + 4);
    float4 b0 = *(const float4*)(beta + c),  b1 = *(const float4*)(beta + c + 4);
    v0.x = (v0.x - mu) * inv * g0.x + b0.x; v0.y = (v0.y - mu) * inv * g0.y + b0.y;
    v0.z = (v0.z - mu) * inv * g0.z + b0.z; v0.w = (v0.w - mu) * inv * g0.w + b0.w;
    v1.x = (v1.x - mu) * inv * g1.x + b1.x; v1.y = (v1.y - mu) * inv * g1.y + b1.y;
    v1.z = (v1.z - mu) * inv * g1.z + b1.z; v1.w = (v1.w - mu) * inv * g1.w + b1.w;

    float4 w00 = *(const float4*)(Wpred + c),      w01 = *(const float4*)(Wpred + c + 4);
    float4 w10 = *(const float4*)(Wpred + CH + c), w11 = *(const float4*)(Wpred + CH + c + 4);
    float d0 = v0.x * w00.x + v0.y * w00.y + v0.z * w00.z + v0.w * w00.w +
               v1.x * w01.x + v1.y * w01.y + v1.z * w01.z + v1.w * w01.w;
    float d1 = v0.x * w10.x + v0.y * w10.y + v0.z * w10.z + v0.w * w10.w +
               v1.x * w11.x + v1.y * w11.y + v1.z * w11.z + v1.w * w11.w;
    #pragma unroll
    for (int o = 16; o; o >>= 1) {
        d0 += __shfl_xor_sync(0xffffffffu, d0, o);
        d1 += __shfl_xor_sync(0xffffffffu, d1, o);
    }

    // stage normalized row into smem (conflict-free float4 stores)
    *(float4*)&tile[wid][c] = v0;
    *(float4*)&tile[wid][c + 4] = v1;

    if (lane == 0) {
        float2 pp = ((const float2*)ppos)[b * NP + n];
        float c0 = d0 + bpred[0] + pp.x;
        float c1 = d1 + bpred[1] + pp.y;
        out_c[(size_t)b * 2 * NP + n] = c0;
        out_c[(size_t)b * 2 * NP + NP + n] = c1;
        ((float2*)out_np)[b * NP + n] = make_float2(c0, c1);
    }
    __syncthreads();

    // coalesced out_x write: thread = channel, 8 consecutive n per store pair
    int col = tid;                          // 0..255
    int n0 = (blockIdx.x * 8) & (NP - 1);
    int bb = (blockIdx.x * 8) >> 11;
    float* ox = out_x + (size_t)bb * CH * NP + (size_t)col * NP + n0;
    float4 o0 = make_float4(tile[0][col], tile[1][col], tile[2][col], tile[3][col]);
    float4 o1 = make_float4(tile[4][col], tile[5][col], tile[6][col], tile[7][col]);
    *(float4*)ox = o0;
    *(float4*)(ox + 4) = o1;
}

// ---------------- launch ----------------
extern "C" void kernel_launch(void* const* d_in, const int* in_sizes, int n_in,
                              void* d_out, int out_size) {
    const float* ptsf   = (const float*)d_in[0];
    const float* ppos   = (const float*)d_in[1];
    const float* imgf   = (const float*)d_in[2];
    const float* ipos   = (const float*)d_in[3];
    const float* ptscls = (const float*)d_in[4];
    const float* imgcls = (const float*)d_in[5];
    const float* Wp  = (const float*)d_in[6];  const float* bp  = (const float*)d_in[7];
    const float* Wi  = (const float*)d_in[8];  const float* bi  = (const float*)d_in[9];
    const float* Wqp = (const float*)d_in[10]; const float* bqp = (const float*)d_in[11];
    const float* Wkp = (const float*)d_in[12]; const float* bkp = (const float*)d_in[13];
    const float* Wout = (const float*)d_in[14]; const float* bout = (const float*)d_in[15];
    const float* gout = (const float*)d_in[16]; const float* betaout = (const float*)d_in[17];
    const float* Wf1 = (const float*)d_in[18]; const float* bf1 = (const float*)d_in[19];
    const float* Wf2 = (const float*)d_in[20]; const float* bf2 = (const float*)d_in[21];
    const float* gln = (const float*)d_in[22]; const float* bln = (const float*)d_in[23];
    const float* Wpred = (const float*)d_in[24]; const float* bpred = (const float*)d_in[25];

    float* out    = (float*)d_out;
    float* out_x  = out;                                   // [2,256,2048]
    float* out_np = out + (size_t)BSZ * CH * NP;           // [2,2048,2]
    float* out_c  = out_np + (size_t)BSZ * NP * 2;         // [2,2,2048]

    const int IPOT_SMEM = NP * (int)sizeof(float) + 8 * NP * (int)sizeof(__half);  // 40 KB
    cudaFuncSetAttribute(k_ipot_persist, cudaFuncAttributeMaxDynamicSharedMemorySize, IPOT_SMEM);

    dim3 tb(32, 8);
    k_cls<<<NROW / 256, 256>>>(ptscls, imgcls);                    // launch 1
    k_transpose<<<dim3(NP / 32, CH / 32, BSZ), tb>>>(ptsf, 0);     // launch 2
    k_transpose<<<dim3(NP / 32, CH / 32, BSZ), tb>>>(imgf, 1);     // launch 3

    // launch 4 (ncu capture slot): ALL 100 IPOT iterations, per-batch barriers
    k_ipot_persist<<<NBLK, 256, IPOT_SMEM>>>(ppos, ipos);

    // projections + positional embeddings
    k_gemm<0><<<dim3(CH / 128, NP / 64, BSZ), 256>>>(Wp, bp, bqp, Wqp, ppos);
    k_gemm<1><<<dim3(NP / 128, CH / 64, BSZ), 256>>>(Wi, bi, bkp, Wkp, ipos);  // *bv folded

    // attention GEMM: img_att = w ⊙ (Q_fp16 @ imf_scaled^T)
    k_gemm<2><<<dim3(CH / 128, NP / 64, BSZ), 256>>>(nullptr, nullptr, nullptr, nullptr, nullptr);
    // out projection + LN
    k_gemm<3><<<dim3(CH / 128, NP / 64, BSZ), 256>>>(Wout, bout, nullptr, nullptr, nullptr);
    k_ln<<<NROW / 8, 256>>>(gout, betaout);
    // FFN
    k_gemm<4><<<dim3(FFNC / 128, NP / 64, BSZ), 256>>>(Wf1, bf1, nullptr, nullptr, nullptr);
    k_gemm<5><<<dim3(CH / 128, NP / 64, BSZ), 256>>>(Wf2, bf2, nullptr, nullptr, nullptr);
    // final LN + head + outputs
    k_final<<<NROW / 8, 256>>>(gln, bln, Wpred, bpred, ppos, out_x, out_np, out_c);
}